// round 3
// baseline (speedup 1.0000x reference)
#include <cuda_runtime.h>
#include <math.h>

#define HW 65536
#define NB 361
#define BN 722
#define MTOK (BN*256)
#define MTOK2 (2*HW)

__device__ float g_Y [MTOK*96];
__device__ float g_Q [MTOK*64];
__device__ float g_K [MTOK*64];
__device__ float g_V [MTOK*96];
__device__ float g_AO[MTOK*96];
__device__ float g_ACC[MTOK2*96];
__device__ float g_YN[MTOK2*96];
__device__ float g_FC1[2*192*HW];
__device__ float g_DW [2*192*HW];

__device__ __forceinline__ int wpos(int i){ int p=i*14; return p>240?240:p; }
__device__ __forceinline__ float divf(int p){
    if (p>=240 && p<254) return 0.5f;
    if (p>=14 && p<240 && (p%14)<2) return 0.5f;
    return 1.0f;
}
__device__ __forceinline__ float gelu_f(float v){
    return 0.5f*v*(1.0f+erff(v*0.70710678118654752f));
}

// K1: windowize + LN1 -> g_Y
__global__ void k_win_ln(const float* __restrict__ x,
                         const float* __restrict__ w1, const float* __restrict__ b1){
    extern __shared__ float sm[];
    float* buf=sm; float* smean=sm+96*257; float* sinvv=smean+256;
    float* sw=sinvv+256; float* sb=sw+96;
    int w=blockIdx.x, b=w/NB, wd=w-b*NB;
    int top=wpos(wd/19), left=wpos(wd%19);
    int t=threadIdx.x;
    if (t<96){ sw[t]=w1[t]; sb[t]=b1[t]; }
    int py=top+(t>>4), px=left+(t&15);
    const float* xp = x + b*96*HW + py*256 + px;
    float s=0.f,s2=0.f;
    #pragma unroll 4
    for (int c=0;c<96;c++){ float v=xp[c*HW]; s+=v; s2+=v*v; buf[c*257+t]=v; }
    float mn=s*(1.f/96.f); float var=s2*(1.f/96.f)-mn*mn;
    smean[t]=mn; sinvv[t]=rsqrtf(var+1e-5f);
    __syncthreads();
    float* yo = g_Y + w*256*96;
    for (int idx=t; idx<256*96; idx+=256){
        int tt=idx/96, cc=idx-tt*96;
        yo[idx]=(buf[cc*257+tt]-smean[tt])*sinvv[tt]*sw[cc]+sb[cc];
    }
}

// generic mainloop: A 64xK (pad KP), W KxNT, 256 thr, 4xTN per thread
template<int K,int KP,int TN>
__device__ __forceinline__ void gmain(const float* As, const float* Ws,
                                      float acc[4][TN], int ty, int tx){
    #pragma unroll 2
    for (int k=0;k<K;k++){
        float a0=As[(ty*4+0)*KP+k], a1=As[(ty*4+1)*KP+k];
        float a2=As[(ty*4+2)*KP+k], a3=As[(ty*4+3)*KP+k];
        const float* wr = Ws + k*(16*TN) + tx*TN;
        #pragma unroll
        for (int j=0;j<TN;j++){
            float wv=wr[j];
            acc[0][j]+=a0*wv; acc[1][j]+=a1*wv; acc[2][j]+=a2*wv; acc[3][j]+=a3*wv;
        }
    }
}

// K2a: Q/K GEMM (N=64), sel 0->g_Q, 1->g_K
__global__ void k_gemm_qk(const float* __restrict__ W, int sel){
    extern __shared__ float sm[];
    float* As=sm; float* Ws=sm+64*97;
    int m0=blockIdx.x*64, tid=threadIdx.x;
    const float* ap=g_Y+(size_t)m0*96;
    for (int idx=tid; idx<64*96; idx+=256){ int r=idx/96; As[r*97+(idx-r*96)]=ap[idx]; }
    for (int idx=tid; idx<96*64; idx+=256) Ws[idx]=W[idx];
    __syncthreads();
    float acc[4][4]={}; int ty=tid>>4, tx=tid&15;
    gmain<96,97,4>(As,Ws,acc,ty,tx);
    float* dst=(sel?g_K:g_Q)+(size_t)m0*64;
    #pragma unroll
    for (int i=0;i<4;i++)
        #pragma unroll
        for (int j=0;j<4;j++) dst[(ty*4+i)*64+tx*4+j]=acc[i][j];
}

// K2b: V GEMM (N=96)
__global__ void k_gemm_v(const float* __restrict__ W){
    extern __shared__ float sm[];
    float* As=sm; float* Ws=sm+64*97;
    int m0=blockIdx.x*64, tid=threadIdx.x;
    const float* ap=g_Y+(size_t)m0*96;
    for (int idx=tid; idx<64*96; idx+=256){ int r=idx/96; As[r*97+(idx-r*96)]=ap[idx]; }
    for (int idx=tid; idx<96*96; idx+=256) Ws[idx]=W[idx];
    __syncthreads();
    float acc[4][6]={}; int ty=tid>>4, tx=tid&15;
    gmain<96,97,6>(As,Ws,acc,ty,tx);
    float* dst=g_V+(size_t)m0*96;
    #pragma unroll
    for (int i=0;i<4;i++)
        #pragma unroll
        for (int j=0;j<6;j++) dst[(ty*4+i)*96+tx*6+j]=acc[i][j];
}

// K3: fused attention per (window, head)
__global__ void k_attn(){
    extern __shared__ float sm[];
    float* qs=sm; float* ks=qs+4096; float* vs=ks+4096;
    float* Ss=vs+6144; float* och=Ss+8320; float* red=och+800;
    float* red2=red+256; float* sinv=red2+256;
    int w=blockIdx.x, h=blockIdx.y, t=threadIdx.x;
    {
        const float4* qp=(const float4*)(g_Q+(size_t)(w*256+t)*64+h*16);
        const float4* kp=(const float4*)(g_K+(size_t)(w*256+t)*64+h*16);
        #pragma unroll
        for (int d4=0;d4<4;d4++){
            float4 qv=qp[d4], kv=kp[d4];
            qs[(d4*4+0)*256+t]=qv.x*0.25f; qs[(d4*4+1)*256+t]=qv.y*0.25f;
            qs[(d4*4+2)*256+t]=qv.z*0.25f; qs[(d4*4+3)*256+t]=qv.w*0.25f;
            ks[(d4*4+0)*256+t]=kv.x; ks[(d4*4+1)*256+t]=kv.y;
            ks[(d4*4+2)*256+t]=kv.z; ks[(d4*4+3)*256+t]=kv.w;
        }
        const float4* vp=(const float4*)(g_V+(size_t)(w*256+t)*96+h*24);
        #pragma unroll
        for (int d4=0;d4<6;d4++){
            float4 vv=vp[d4];
            vs[(d4*4+0)*256+t]=vv.x; vs[(d4*4+1)*256+t]=vv.y;
            vs[(d4*4+2)*256+t]=vv.z; vs[(d4*4+3)*256+t]=vv.w;
        }
    }
    __syncthreads();
    int ty=t>>4, tx=t&15, row=t&31, part=t>>5;
    for (int ch=0; ch<8; ch++){
        int qb=ch*32;
        float acc[2][16];
        #pragma unroll
        for (int i=0;i<2;i++)
            #pragma unroll
            for (int j=0;j<16;j++) acc[i][j]=0.f;
        #pragma unroll 2
        for (int d=0;d<16;d++){
            float a0=qs[d*256+qb+ty*2], a1=qs[d*256+qb+ty*2+1];
            const float4* krow=(const float4*)(ks+d*256+tx*16);
            #pragma unroll
            for (int j4=0;j4<4;j4++){
                float4 kv=krow[j4];
                acc[0][j4*4+0]+=a0*kv.x; acc[0][j4*4+1]+=a0*kv.y;
                acc[0][j4*4+2]+=a0*kv.z; acc[0][j4*4+3]+=a0*kv.w;
                acc[1][j4*4+0]+=a1*kv.x; acc[1][j4*4+1]+=a1*kv.y;
                acc[1][j4*4+2]+=a1*kv.z; acc[1][j4*4+3]+=a1*kv.w;
            }
        }
        #pragma unroll
        for (int i=0;i<2;i++)
            #pragma unroll
            for (int j4=0;j4<4;j4++)
                *(float4*)&Ss[(ty*2+i)*260+tx*16+j4*4]=
                    make_float4(acc[i][j4*4],acc[i][j4*4+1],acc[i][j4*4+2],acc[i][j4*4+3]);
        __syncthreads();
        float* srow=Ss+row*260+part*32;
        float mx=-1e30f;
        #pragma unroll
        for (int kq=0;kq<8;kq++){
            float4 v4=*(const float4*)&srow[kq*4];
            mx=fmaxf(mx,fmaxf(fmaxf(v4.x,v4.y),fmaxf(v4.z,v4.w)));
        }
        red[t]=mx; __syncthreads();
        mx=red[row];
        #pragma unroll
        for (int pp=1;pp<8;pp++) mx=fmaxf(mx,red[pp*32+row]);
        float ssum=0.f;
        #pragma unroll
        for (int kq=0;kq<8;kq++){
            float4 v4=*(const float4*)&srow[kq*4];
            v4.x=__expf(v4.x-mx); v4.y=__expf(v4.y-mx);
            v4.z=__expf(v4.z-mx); v4.w=__expf(v4.w-mx);
            *(float4*)&srow[kq*4]=v4;
            ssum+=v4.x+v4.y+v4.z+v4.w;
        }
        red2[t]=ssum; __syncthreads();
        if (t<32){
            float s=red2[t];
            #pragma unroll
            for (int pp=1;pp<8;pp++) s+=red2[pp*32+t];
            sinv[t]=1.f/s;
        }
        __syncthreads();
        float a0=0.f,a1=0.f,a2=0.f;
        const float* prow=Ss+row*260;
        const float* v0=vs+(part*3+0)*256;
        const float* v1=vs+(part*3+1)*256;
        const float* v2=vs+(part*3+2)*256;
        #pragma unroll 4
        for (int kk=0;kk<256;kk+=4){
            float4 p4=*(const float4*)&prow[kk];
            float4 va=*(const float4*)&v0[kk];
            float4 vb=*(const float4*)&v1[kk];
            float4 vc=*(const float4*)&v2[kk];
            a0+=p4.x*va.x+p4.y*va.y+p4.z*va.z+p4.w*va.w;
            a1+=p4.x*vb.x+p4.y*vb.y+p4.z*vb.z+p4.w*vb.w;
            a2+=p4.x*vc.x+p4.y*vc.y+p4.z*vc.z+p4.w*vc.w;
        }
        float sc=sinv[row];
        och[row*25+part*3+0]=a0*sc;
        och[row*25+part*3+1]=a1*sc;
        och[row*25+part*3+2]=a2*sc;
        __syncthreads();
        float* aop=g_AO+(size_t)(w*256+qb)*96+h*24;
        for (int idx=t; idx<768; idx+=256){
            int t2=idx/24, d2=idx-t2*24;
            aop[t2*96+d2]=och[t2*25+d2];
        }
        __syncthreads();
    }
}

// K4: init ACC token-major with x * (1/f)
__global__ void k_init_acc(const float* __restrict__ x){
    extern __shared__ float buf[];
    int blk=blockIdx.x, b=blk>>8, y=blk&255, t=threadIdx.x;
    const float* xp=x+(size_t)b*96*HW+y*256+t;
    for (int c=0;c<96;c++) buf[c*257+t]=xp[c*HW];
    __syncthreads();
    float iv=(divf(y)==0.5f?2.f:1.f)*(divf(t)==0.5f?2.f:1.f);
    float* dst=g_ACC+(size_t)(b*HW+y*256+t)*96;
    for (int c=0;c<96;c+=4){
        float4 o; o.x=buf[c*257+t]*iv; o.y=buf[(c+1)*257+t]*iv;
        o.z=buf[(c+2)*257+t]*iv; o.w=buf[(c+3)*257+t]*iv;
        *(float4*)(dst+c)=o;
    }
}

// K5: proj GEMM + overlap-add scatter into ACC
__global__ void k_gemm_proj(const float* __restrict__ W){
    extern __shared__ float sm[];
    float* As=sm; float* Ws=sm+64*97;
    int m0=blockIdx.x*64, tid=threadIdx.x;
    const float* ap=g_AO+(size_t)m0*96;
    for (int idx=tid; idx<64*96; idx+=256){ int r=idx/96; As[r*97+(idx-r*96)]=ap[idx]; }
    for (int idx=tid; idx<96*96; idx+=256) Ws[idx]=W[idx];
    __syncthreads();
    float acc[4][6]={}; int ty=tid>>4, tx=tid&15;
    gmain<96,97,6>(As,Ws,acc,ty,tx);
    int w=m0>>8, b=w/NB, wd=w-b*NB;
    int top=wpos(wd/19), left=wpos(wd%19);
    int tb=m0&255;
    #pragma unroll
    for (int i=0;i<4;i++){
        int tt=tb+ty*4+i;
        int py=top+(tt>>4), px=left+(tt&15);
        float* dst=g_ACC+(size_t)(b*HW+py*256+px)*96+tx*6;
        #pragma unroll
        for (int j=0;j<6;j++) atomicAdd(dst+j,acc[i][j]);
    }
}

// K6: LN2, token per thread
__global__ void k_ln2(const float* __restrict__ w2, const float* __restrict__ b2){
    int m=blockIdx.x*256+threadIdx.x;
    int p=m&65535;
    float f=divf(p>>8)*divf(p&255);
    const float4* a4=(const float4*)(g_ACC+(size_t)m*96);
    float s=0.f,s2=0.f;
    #pragma unroll 4
    for (int q=0;q<24;q++){
        float4 v=a4[q];
        v.x*=f; v.y*=f; v.z*=f; v.w*=f;
        s+=v.x+v.y+v.z+v.w;
        s2+=v.x*v.x+v.y*v.y+v.z*v.z+v.w*v.w;
    }
    float mn=s*(1.f/96.f); float inv=rsqrtf(s2*(1.f/96.f)-mn*mn+1e-5f);
    float4* yo=(float4*)(g_YN+(size_t)m*96);
    const float4* w4=(const float4*)w2; const float4* bb4=(const float4*)b2;
    #pragma unroll 4
    for (int q=0;q<24;q++){
        float4 v=a4[q]; float4 wv=w4[q]; float4 bv=bb4[q];
        v.x=(v.x*f-mn)*inv*wv.x+bv.x; v.y=(v.y*f-mn)*inv*wv.y+bv.y;
        v.z=(v.z*f-mn)*inv*wv.z+bv.z; v.w=(v.w*f-mn)*inv*wv.w+bv.w;
        yo[q]=v;
    }
}

// K7: fc1 GEMM half (n0=0 or 96), gelu, channel-major store
__global__ void k_fc1(const float* __restrict__ W, const float* __restrict__ bias, int n0){
    extern __shared__ float sm[];
    float* As=sm; float* Cs=sm; float* Ws=sm+6240;
    int m0=blockIdx.x*64, tid=threadIdx.x;
    const float* ap=g_YN+(size_t)m0*96;
    for (int idx=tid; idx<64*96; idx+=256){ int r=idx/96; As[r*97+(idx-r*96)]=ap[idx]; }
    for (int idx=tid; idx<96*96; idx+=256){ int k=idx/96; Ws[idx]=W[k*192+n0+(idx-k*96)]; }
    __syncthreads();
    float acc[4][6]={}; int ty=tid>>4, tx=tid&15;
    gmain<96,97,6>(As,Ws,acc,ty,tx);
    __syncthreads();
    #pragma unroll
    for (int i=0;i<4;i++)
        #pragma unroll
        for (int j=0;j<6;j++)
            Cs[(tx*6+j)*65+ty*4+i]=gelu_f(acc[i][j]+bias[n0+tx*6+j]);
    __syncthreads();
    int b=m0>>16, p0=m0&65535;
    for (int idx=tid; idx<96*64; idx+=256){
        int c=idx>>6, r=idx&63;
        g_FC1[(size_t)(b*192+n0+c)*HW+p0+r]=Cs[c*65+r];
    }
}

// K8: 5x5 depthwise conv + gelu
__global__ void k_dw(const float* __restrict__ dwW, const float* __restrict__ dwB){
    __shared__ float swt[25];
    __shared__ float tile[12*260];
    int bc=blockIdx.x, ch=bc%192;
    int y0=blockIdx.y*8, t=threadIdx.x;
    if (t<25) swt[t]=dwW[ch*25+t];
    const float* src=g_FC1+(size_t)bc*HW;
    for (int idx=t; idx<3120; idx+=256){
        int rr=idx/260, cc=idx-rr*260;
        int gy=y0-2+rr, gx=cc-2;
        tile[idx]=(gy>=0 && gy<256 && (unsigned)gx<256u)?src[gy*256+gx]:0.f;
    }
    __syncthreads();
    float bias=dwB[ch];
    #pragma unroll
    for (int r=0;r<8;r++){
        float a=0.f;
        #pragma unroll
        for (int ky=0;ky<5;ky++)
            #pragma unroll
            for (int kx=0;kx<5;kx++)
                a+=tile[(r+ky)*260+t+kx]*swt[ky*5+kx];
        g_DW[(size_t)bc*HW+(y0+r)*256+t]=gelu_f(a+bias);
    }
}

// K9: fc2 GEMM (K=192) + bias + residual, NCHW store
__global__ void k_fc2(const float* __restrict__ W, const float* __restrict__ bias,
                      float* __restrict__ out){
    extern __shared__ float sm[];
    float* As=sm; float* Cs=sm; float* Ws=sm+64*193;
    int m0=blockIdx.x*64, tid=threadIdx.x;
    int b=m0>>16, p0=m0&65535;
    for (int idx=tid; idx<64*192; idx+=256){
        int k=idx>>6, r=idx&63;
        size_t g=(size_t)(b*192+k)*HW+p0+r;
        As[r*193+k]=g_FC1[g]+g_DW[g];
    }
    for (int idx=tid; idx<192*96; idx+=256) Ws[idx]=W[idx];
    __syncthreads();
    float acc[4][6]={}; int ty=tid>>4, tx=tid&15;
    gmain<192,193,6>(As,Ws,acc,ty,tx);
    __syncthreads();
    #pragma unroll
    for (int i=0;i<4;i++){
        int p=p0+ty*4+i;
        float f=divf(p>>8)*divf(p&255);
        const float* arow=g_ACC+(size_t)(b*HW+p)*96;
        #pragma unroll
        for (int j=0;j<6;j++){
            int c=tx*6+j;
            Cs[c*65+ty*4+i]=acc[i][j]+bias[c]+arow[c]*f;
        }
    }
    __syncthreads();
    for (int idx=tid; idx<96*64; idx+=256){
        int c=idx>>6, r=idx&63;
        out[(size_t)(b*96+c)*HW+p0+r]=Cs[c*65+r];
    }
}

static void setsm(const void* f, int bytes){
    cudaFuncSetAttribute(f, cudaFuncAttributeMaxDynamicSharedMemorySize, bytes);
}

extern "C" void kernel_launch(void* const* d_in, const int* in_sizes, int n_in,
                              void* d_out, int out_size){
    const float* x   =(const float*)d_in[0];
    const float* n1w =(const float*)d_in[1];
    const float* n1b =(const float*)d_in[2];
    const float* wq  =(const float*)d_in[3];
    const float* wk  =(const float*)d_in[4];
    const float* wv  =(const float*)d_in[5];
    const float* wpj =(const float*)d_in[6];
    const float* n2w =(const float*)d_in[7];
    const float* n2b =(const float*)d_in[8];
    const float* f1w =(const float*)d_in[9];
    const float* f1b =(const float*)d_in[10];
    const float* dww =(const float*)d_in[11];
    const float* dwb =(const float*)d_in[12];
    const float* f2w =(const float*)d_in[13];
    const float* f2b =(const float*)d_in[14];
    float* out=(float*)d_out;

    setsm((const void*)k_win_ln, 101504);
    setsm((const void*)k_gemm_qk, 49408);
    setsm((const void*)k_gemm_v, 61696);
    setsm((const void*)k_attn, 96000);
    setsm((const void*)k_init_acc, 98688);
    setsm((const void*)k_gemm_proj, 61696);
    setsm((const void*)k_fc1, 61824);
    setsm((const void*)k_fc2, 123136);

    k_win_ln<<<BN,256,101504>>>(x,n1w,n1b);
    k_gemm_qk<<<MTOK/64,256,49408>>>(wq,0);
    k_gemm_qk<<<MTOK/64,256,49408>>>(wk,1);
    k_gemm_v<<<MTOK/64,256,61696>>>(wv);
    k_attn<<<dim3(BN,4),256,96000>>>();
    k_init_acc<<<512,256,98688>>>(x);
    k_gemm_proj<<<MTOK/64,256,61696>>>(wpj);
    k_ln2<<<512,256>>>(n2w,n2b);
    k_fc1<<<MTOK2/64,256,61824>>>(f1w,f1b,0);
    k_fc1<<<MTOK2/64,256,61824>>>(f1w,f1b,96);
    k_dw<<<dim3(384,32),256>>>(dww,dwb);
    k_fc2<<<MTOK2/64,256,123136>>>(f2w,f2b,out);
}

// round 4
// speedup vs baseline: 1.0088x; 1.0088x over previous
#include <cuda_runtime.h>
#include <math.h>

#define HW 65536
#define NB 361
#define BN 722
#define MTOK (BN*256)
#define MTOK2 (2*HW)

__device__ float g_Y [MTOK*96];
__device__ float g_Q [MTOK*64];
__device__ float g_K [MTOK*64];
__device__ float g_V [MTOK*96];
__device__ float g_AO[MTOK*96];
__device__ float g_ACC[MTOK2*96];
__device__ float g_YN[MTOK2*96];
__device__ float g_FC1[2*192*HW];
__device__ float g_DW [2*192*HW];

__device__ __forceinline__ int wpos(int i){ int p=i*14; return p>240?240:p; }
__device__ __forceinline__ float divf(int p){
    if (p>=240 && p<254) return 0.5f;
    if (p>=14 && p<240 && (p%14)<2) return 0.5f;
    return 1.0f;
}
__device__ __forceinline__ float gelu_f(float v){
    return 0.5f*v*(1.0f+erff(v*0.70710678118654752f));
}

// K1: windowize + LN1 -> g_Y
__global__ void k_win_ln(const float* __restrict__ x,
                         const float* __restrict__ w1, const float* __restrict__ b1){
    extern __shared__ float sm[];
    float* buf=sm; float* smean=sm+96*257; float* sinvv=smean+256;
    float* sw=sinvv+256; float* sb=sw+96;
    int w=blockIdx.x, b=w/NB, wd=w-b*NB;
    int top=wpos(wd/19), left=wpos(wd%19);
    int t=threadIdx.x;
    if (t<96){ sw[t]=w1[t]; sb[t]=b1[t]; }
    int py=top+(t>>4), px=left+(t&15);
    const float* xp = x + b*96*HW + py*256 + px;
    float s=0.f,s2=0.f;
    #pragma unroll 4
    for (int c=0;c<96;c++){ float v=xp[c*HW]; s+=v; s2+=v*v; buf[c*257+t]=v; }
    float mn=s*(1.f/96.f); float var=s2*(1.f/96.f)-mn*mn;
    smean[t]=mn; sinvv[t]=rsqrtf(var+1e-5f);
    __syncthreads();
    float* yo = g_Y + w*256*96;
    for (int idx=t; idx<256*96; idx+=256){
        int tt=idx/96, cc=idx-tt*96;
        yo[idx]=(buf[cc*257+tt]-smean[tt])*sinvv[tt]*sw[cc]+sb[cc];
    }
}

// generic mainloop: A 64xK (pad KP), W KxNT, 256 thr, 4xTN per thread
template<int K,int KP,int TN>
__device__ __forceinline__ void gmain(const float* As, const float* Ws,
                                      float acc[4][TN], int ty, int tx){
    #pragma unroll 2
    for (int k=0;k<K;k++){
        float a0=As[(ty*4+0)*KP+k], a1=As[(ty*4+1)*KP+k];
        float a2=As[(ty*4+2)*KP+k], a3=As[(ty*4+3)*KP+k];
        const float* wr = Ws + k*(16*TN) + tx*TN;
        #pragma unroll
        for (int j=0;j<TN;j++){
            float wv=wr[j];
            acc[0][j]+=a0*wv; acc[1][j]+=a1*wv; acc[2][j]+=a2*wv; acc[3][j]+=a3*wv;
        }
    }
}

// K2a: Q/K GEMM (N=64), sel 0->g_Q, 1->g_K
__global__ void k_gemm_qk(const float* __restrict__ W, int sel){
    extern __shared__ float sm[];
    float* As=sm; float* Ws=sm+64*97;
    int m0=blockIdx.x*64, tid=threadIdx.x;
    const float* ap=g_Y+(size_t)m0*96;
    for (int idx=tid; idx<64*96; idx+=256){ int r=idx/96; As[r*97+(idx-r*96)]=ap[idx]; }
    for (int idx=tid; idx<96*64; idx+=256) Ws[idx]=W[idx];
    __syncthreads();
    float acc[4][4]={}; int ty=tid>>4, tx=tid&15;
    gmain<96,97,4>(As,Ws,acc,ty,tx);
    float* dst=(sel?g_K:g_Q)+(size_t)m0*64;
    #pragma unroll
    for (int i=0;i<4;i++)
        #pragma unroll
        for (int j=0;j<4;j++) dst[(ty*4+i)*64+tx*4+j]=acc[i][j];
}

// K2b: V GEMM (N=96)
__global__ void k_gemm_v(const float* __restrict__ W){
    extern __shared__ float sm[];
    float* As=sm; float* Ws=sm+64*97;
    int m0=blockIdx.x*64, tid=threadIdx.x;
    const float* ap=g_Y+(size_t)m0*96;
    for (int idx=tid; idx<64*96; idx+=256){ int r=idx/96; As[r*97+(idx-r*96)]=ap[idx]; }
    for (int idx=tid; idx<96*96; idx+=256) Ws[idx]=W[idx];
    __syncthreads();
    float acc[4][6]={}; int ty=tid>>4, tx=tid&15;
    gmain<96,97,6>(As,Ws,acc,ty,tx);
    float* dst=g_V+(size_t)m0*96;
    #pragma unroll
    for (int i=0;i<4;i++)
        #pragma unroll
        for (int j=0;j<6;j++) dst[(ty*4+i)*96+tx*6+j]=acc[i][j];
}

// K3: fused attention per (window, head)
__global__ void k_attn(){
    extern __shared__ float sm[];
    float* qs=sm; float* ks=qs+4096; float* vs=ks+4096;
    float* Ss=vs+6144; float* och=Ss+8320; float* red=och+800;
    float* red2=red+256; float* sinv=red2+256;
    int w=blockIdx.x, h=blockIdx.y, t=threadIdx.x;
    {
        const float4* qp=(const float4*)(g_Q+(size_t)(w*256+t)*64+h*16);
        const float4* kp=(const float4*)(g_K+(size_t)(w*256+t)*64+h*16);
        #pragma unroll
        for (int d4=0;d4<4;d4++){
            float4 qv=qp[d4], kv=kp[d4];
            qs[(d4*4+0)*256+t]=qv.x*0.25f; qs[(d4*4+1)*256+t]=qv.y*0.25f;
            qs[(d4*4+2)*256+t]=qv.z*0.25f; qs[(d4*4+3)*256+t]=qv.w*0.25f;
            ks[(d4*4+0)*256+t]=kv.x; ks[(d4*4+1)*256+t]=kv.y;
            ks[(d4*4+2)*256+t]=kv.z; ks[(d4*4+3)*256+t]=kv.w;
        }
        const float4* vp=(const float4*)(g_V+(size_t)(w*256+t)*96+h*24);
        #pragma unroll
        for (int d4=0;d4<6;d4++){
            float4 vv=vp[d4];
            vs[(d4*4+0)*256+t]=vv.x; vs[(d4*4+1)*256+t]=vv.y;
            vs[(d4*4+2)*256+t]=vv.z; vs[(d4*4+3)*256+t]=vv.w;
        }
    }
    __syncthreads();
    int ty=t>>4, tx=t&15, row=t&31, part=t>>5;
    for (int ch=0; ch<8; ch++){
        int qb=ch*32;
        float acc[2][16];
        #pragma unroll
        for (int i=0;i<2;i++)
            #pragma unroll
            for (int j=0;j<16;j++) acc[i][j]=0.f;
        #pragma unroll 2
        for (int d=0;d<16;d++){
            float a0=qs[d*256+qb+ty*2], a1=qs[d*256+qb+ty*2+1];
            const float4* krow=(const float4*)(ks+d*256+tx*16);
            #pragma unroll
            for (int j4=0;j4<4;j4++){
                float4 kv=krow[j4];
                acc[0][j4*4+0]+=a0*kv.x; acc[0][j4*4+1]+=a0*kv.y;
                acc[0][j4*4+2]+=a0*kv.z; acc[0][j4*4+3]+=a0*kv.w;
                acc[1][j4*4+0]+=a1*kv.x; acc[1][j4*4+1]+=a1*kv.y;
                acc[1][j4*4+2]+=a1*kv.z; acc[1][j4*4+3]+=a1*kv.w;
            }
        }
        #pragma unroll
        for (int i=0;i<2;i++)
            #pragma unroll
            for (int j4=0;j4<4;j4++)
                *(float4*)&Ss[(ty*2+i)*260+tx*16+j4*4]=
                    make_float4(acc[i][j4*4],acc[i][j4*4+1],acc[i][j4*4+2],acc[i][j4*4+3]);
        __syncthreads();
        float* srow=Ss+row*260+part*32;
        float mx=-1e30f;
        #pragma unroll
        for (int kq=0;kq<8;kq++){
            float4 v4=*(const float4*)&srow[kq*4];
            mx=fmaxf(mx,fmaxf(fmaxf(v4.x,v4.y),fmaxf(v4.z,v4.w)));
        }
        red[t]=mx; __syncthreads();
        mx=red[row];
        #pragma unroll
        for (int pp=1;pp<8;pp++) mx=fmaxf(mx,red[pp*32+row]);
        float ssum=0.f;
        #pragma unroll
        for (int kq=0;kq<8;kq++){
            float4 v4=*(const float4*)&srow[kq*4];
            v4.x=__expf(v4.x-mx); v4.y=__expf(v4.y-mx);
            v4.z=__expf(v4.z-mx); v4.w=__expf(v4.w-mx);
            *(float4*)&srow[kq*4]=v4;
            ssum+=v4.x+v4.y+v4.z+v4.w;
        }
        red2[t]=ssum; __syncthreads();
        if (t<32){
            float s=red2[t];
            #pragma unroll
            for (int pp=1;pp<8;pp++) s+=red2[pp*32+t];
            sinv[t]=1.f/s;
        }
        __syncthreads();
        float a0=0.f,a1=0.f,a2=0.f;
        const float* prow=Ss+row*260;
        const float* v0=vs+(part*3+0)*256;
        const float* v1=vs+(part*3+1)*256;
        const float* v2=vs+(part*3+2)*256;
        #pragma unroll 4
        for (int kk=0;kk<256;kk+=4){
            float4 p4=*(const float4*)&prow[kk];
            float4 va=*(const float4*)&v0[kk];
            float4 vb=*(const float4*)&v1[kk];
            float4 vc=*(const float4*)&v2[kk];
            a0+=p4.x*va.x+p4.y*va.y+p4.z*va.z+p4.w*va.w;
            a1+=p4.x*vb.x+p4.y*vb.y+p4.z*vb.z+p4.w*vb.w;
            a2+=p4.x*vc.x+p4.y*vc.y+p4.z*vc.z+p4.w*vc.w;
        }
        float sc=sinv[row];
        och[row*25+part*3+0]=a0*sc;
        och[row*25+part*3+1]=a1*sc;
        och[row*25+part*3+2]=a2*sc;
        __syncthreads();
        float* aop=g_AO+(size_t)(w*256+qb)*96+h*24;
        for (int idx=t; idx<768; idx+=256){
            int t2=idx/24, d2=idx-t2*24;
            aop[t2*96+d2]=och[t2*25+d2];
        }
        __syncthreads();
    }
}

// K4: init ACC token-major with x * (1/f)
__global__ void k_init_acc(const float* __restrict__ x){
    extern __shared__ float buf[];
    int blk=blockIdx.x, b=blk>>8, y=blk&255, t=threadIdx.x;
    const float* xp=x+(size_t)b*96*HW+y*256+t;
    for (int c=0;c<96;c++) buf[c*257+t]=xp[c*HW];
    __syncthreads();
    float iv=(divf(y)==0.5f?2.f:1.f)*(divf(t)==0.5f?2.f:1.f);
    float* dst=g_ACC+(size_t)(b*HW+y*256+t)*96;
    for (int c=0;c<96;c+=4){
        float4 o; o.x=buf[c*257+t]*iv; o.y=buf[(c+1)*257+t]*iv;
        o.z=buf[(c+2)*257+t]*iv; o.w=buf[(c+3)*257+t]*iv;
        *(float4*)(dst+c)=o;
    }
}

// K5: proj GEMM + overlap-add scatter into ACC
__global__ void k_gemm_proj(const float* __restrict__ W){
    extern __shared__ float sm[];
    float* As=sm; float* Ws=sm+64*97;
    int m0=blockIdx.x*64, tid=threadIdx.x;
    const float* ap=g_AO+(size_t)m0*96;
    for (int idx=tid; idx<64*96; idx+=256){ int r=idx/96; As[r*97+(idx-r*96)]=ap[idx]; }
    for (int idx=tid; idx<96*96; idx+=256) Ws[idx]=W[idx];
    __syncthreads();
    float acc[4][6]={}; int ty=tid>>4, tx=tid&15;
    gmain<96,97,6>(As,Ws,acc,ty,tx);
    int w=m0>>8, b=w/NB, wd=w-b*NB;
    int top=wpos(wd/19), left=wpos(wd%19);
    int tb=m0&255;
    #pragma unroll
    for (int i=0;i<4;i++){
        int tt=tb+ty*4+i;
        int py=top+(tt>>4), px=left+(tt&15);
        float* dst=g_ACC+(size_t)(b*HW+py*256+px)*96+tx*6;
        #pragma unroll
        for (int j=0;j<6;j++) atomicAdd(dst+j,acc[i][j]);
    }
}

// K6: LN2, token per thread
__global__ void k_ln2(const float* __restrict__ w2, const float* __restrict__ b2){
    int m=blockIdx.x*256+threadIdx.x;
    int p=m&65535;
    float f=divf(p>>8)*divf(p&255);
    const float4* a4=(const float4*)(g_ACC+(size_t)m*96);
    float s=0.f,s2=0.f;
    #pragma unroll 4
    for (int q=0;q<24;q++){
        float4 v=a4[q];
        v.x*=f; v.y*=f; v.z*=f; v.w*=f;
        s+=v.x+v.y+v.z+v.w;
        s2+=v.x*v.x+v.y*v.y+v.z*v.z+v.w*v.w;
    }
    float mn=s*(1.f/96.f); float inv=rsqrtf(s2*(1.f/96.f)-mn*mn+1e-5f);
    float4* yo=(float4*)(g_YN+(size_t)m*96);
    const float4* w4=(const float4*)w2; const float4* bb4=(const float4*)b2;
    #pragma unroll 4
    for (int q=0;q<24;q++){
        float4 v=a4[q]; float4 wv=w4[q]; float4 bv=bb4[q];
        v.x=(v.x*f-mn)*inv*wv.x+bv.x; v.y=(v.y*f-mn)*inv*wv.y+bv.y;
        v.z=(v.z*f-mn)*inv*wv.z+bv.z; v.w=(v.w*f-mn)*inv*wv.w+bv.w;
        yo[q]=v;
    }
}

// K7: fc1 GEMM half (n0=0 or 96), gelu, channel-major store
__global__ void k_fc1(const float* __restrict__ W, const float* __restrict__ bias, int n0){
    extern __shared__ float sm[];
    float* As=sm; float* Cs=sm; float* Ws=sm+6240;
    int m0=blockIdx.x*64, tid=threadIdx.x;
    const float* ap=g_YN+(size_t)m0*96;
    for (int idx=tid; idx<64*96; idx+=256){ int r=idx/96; As[r*97+(idx-r*96)]=ap[idx]; }
    for (int idx=tid; idx<96*96; idx+=256){ int k=idx/96; Ws[idx]=W[k*192+n0+(idx-k*96)]; }
    __syncthreads();
    float acc[4][6]={}; int ty=tid>>4, tx=tid&15;
    gmain<96,97,6>(As,Ws,acc,ty,tx);
    __syncthreads();
    #pragma unroll
    for (int i=0;i<4;i++)
        #pragma unroll
        for (int j=0;j<6;j++)
            Cs[(tx*6+j)*65+ty*4+i]=gelu_f(acc[i][j]+bias[n0+tx*6+j]);
    __syncthreads();
    int b=m0>>16, p0=m0&65535;
    for (int idx=tid; idx<96*64; idx+=256){
        int c=idx>>6, r=idx&63;
        g_FC1[(size_t)(b*192+n0+c)*HW+p0+r]=Cs[c*65+r];
    }
}

// K8: 5x5 depthwise conv + gelu
__global__ void k_dw(const float* __restrict__ dwW, const float* __restrict__ dwB){
    __shared__ float swt[25];
    __shared__ float tile[12*260];
    int bc=blockIdx.x, ch=bc%192;
    int y0=blockIdx.y*8, t=threadIdx.x;
    if (t<25) swt[t]=dwW[ch*25+t];
    const float* src=g_FC1+(size_t)bc*HW;
    for (int idx=t; idx<3120; idx+=256){
        int rr=idx/260, cc=idx-rr*260;
        int gy=y0-2+rr, gx=cc-2;
        tile[idx]=(gy>=0 && gy<256 && (unsigned)gx<256u)?src[gy*256+gx]:0.f;
    }
    __syncthreads();
    float bias=dwB[ch];
    #pragma unroll
    for (int r=0;r<8;r++){
        float a=0.f;
        #pragma unroll
        for (int ky=0;ky<5;ky++)
            #pragma unroll
            for (int kx=0;kx<5;kx++)
                a+=tile[(r+ky)*260+t+kx]*swt[ky*5+kx];
        g_DW[(size_t)bc*HW+(y0+r)*256+t]=gelu_f(a+bias);
    }
}

// K9: fc2 GEMM (K=192) + bias + residual, NCHW store
__global__ void k_fc2(const float* __restrict__ W, const float* __restrict__ bias,
                      float* __restrict__ out){
    extern __shared__ float sm[];
    float* As=sm; float* Cs=sm; float* Ws=sm+64*193;
    int m0=blockIdx.x*64, tid=threadIdx.x;
    int b=m0>>16, p0=m0&65535;
    for (int idx=tid; idx<64*192; idx+=256){
        int k=idx>>6, r=idx&63;
        size_t g=(size_t)(b*192+k)*HW+p0+r;
        As[r*193+k]=g_FC1[g]+g_DW[g];
    }
    for (int idx=tid; idx<192*96; idx+=256) Ws[idx]=W[idx];
    __syncthreads();
    float acc[4][6]={}; int ty=tid>>4, tx=tid&15;
    gmain<192,193,6>(As,Ws,acc,ty,tx);
    __syncthreads();
    #pragma unroll
    for (int i=0;i<4;i++){
        int p=p0+ty*4+i;
        float f=divf(p>>8)*divf(p&255);
        const float* arow=g_ACC+(size_t)(b*HW+p)*96;
        #pragma unroll
        for (int j=0;j<6;j++){
            int c=tx*6+j;
            Cs[c*65+ty*4+i]=acc[i][j]+bias[c]+arow[c]*f;
        }
    }
    __syncthreads();
    for (int idx=tid; idx<96*64; idx+=256){
        int c=idx>>6, r=idx&63;
        out[(size_t)(b*96+c)*HW+p0+r]=Cs[c*65+r];
    }
}

static void setsm(const void* f, int bytes){
    cudaFuncSetAttribute(f, cudaFuncAttributeMaxDynamicSharedMemorySize, bytes);
}

extern "C" void kernel_launch(void* const* d_in, const int* in_sizes, int n_in,
                              void* d_out, int out_size){
    const float* x   =(const float*)d_in[0];
    const float* n1w =(const float*)d_in[1];
    const float* n1b =(const float*)d_in[2];
    const float* wq  =(const float*)d_in[3];
    const float* wk  =(const float*)d_in[4];
    const float* wv  =(const float*)d_in[5];
    const float* wpj =(const float*)d_in[6];
    const float* n2w =(const float*)d_in[7];
    const float* n2b =(const float*)d_in[8];
    const float* f1w =(const float*)d_in[9];
    const float* f1b =(const float*)d_in[10];
    const float* dww =(const float*)d_in[11];
    const float* dwb =(const float*)d_in[12];
    const float* f2w =(const float*)d_in[13];
    const float* f2b =(const float*)d_in[14];
    float* out=(float*)d_out;

    setsm((const void*)k_win_ln, 101504);
    setsm((const void*)k_gemm_qk, 49408);
    setsm((const void*)k_gemm_v, 61696);
    setsm((const void*)k_attn, 96000);
    setsm((const void*)k_init_acc, 98688);
    setsm((const void*)k_gemm_proj, 61696);
    setsm((const void*)k_fc1, 61824);
    setsm((const void*)k_fc2, 123136);

    k_win_ln<<<BN,256,101504>>>(x,n1w,n1b);
    k_gemm_qk<<<MTOK/64,256,49408>>>(wq,0);
    k_gemm_qk<<<MTOK/64,256,49408>>>(wk,1);
    k_gemm_v<<<MTOK/64,256,61696>>>(wv);
    k_attn<<<dim3(BN,4),256,96000>>>();
    k_init_acc<<<512,256,98688>>>(x);
    k_gemm_proj<<<MTOK/64,256,61696>>>(wpj);
    k_ln2<<<512,256>>>(n2w,n2b);
    k_fc1<<<MTOK2/64,256,61824>>>(f1w,f1b,0);
    k_fc1<<<MTOK2/64,256,61824>>>(f1w,f1b,96);
    k_dw<<<dim3(384,32),256>>>(dww,dwb);
    k_fc2<<<MTOK2/64,256,123136>>>(f2w,f2b,out);
}

// round 6
// speedup vs baseline: 1.5111x; 1.4980x over previous
#include <cuda_runtime.h>
#include <math.h>

#define HW 65536
#define NB 361
#define BN 722
#define MTOK (BN*256)
#define MTOK2 (2*HW)

__device__ float g_Y [MTOK*96];
__device__ float g_Q [MTOK*64];
__device__ float g_K [MTOK*64];
__device__ float g_V [MTOK*96];
__device__ float g_AO[MTOK*96];
__device__ float g_PO[MTOK*96];
__device__ float g_ACC[MTOK2*96];
__device__ float g_X2C[MTOK2*96];
__device__ float g_YN[MTOK2*96];
__device__ float g_FC1[2*192*HW];
__device__ float g_DW [2*192*HW];
__device__ float g_WT [224*96 + 96*96 + 192*96 + 96*192];

__device__ __forceinline__ int wpos(int i){ int p=i*14; return p>240?240:p; }
__device__ __forceinline__ float gelu_f(float v){
    return 0.5f*v*(1.0f+erff(v*0.70710678118654752f));
}
__device__ __forceinline__ float tf32r(float x){
    float y; asm("cvt.rna.tf32.f32 %0, %1;" : "=f"(y) : "f"(x)); return y;
}
#define MMA_T(acc,a0,a1,a2,a3,b0,b1) \
    asm volatile("mma.sync.aligned.m16n8k8.row.col.f32.tf32.tf32.f32 " \
        "{%0,%1,%2,%3},{%4,%5,%6,%7},{%8,%9},{%0,%1,%2,%3};" \
        : "+f"(acc[0]),"+f"(acc[1]),"+f"(acc[2]),"+f"(acc[3]) \
        : "r"(a0),"r"(a1),"r"(a2),"r"(a3),"r"(b0),"r"(b1))

// K0: transpose weights to [n][k] + tf32 round
__global__ void k_prep(const float* __restrict__ wq, const float* __restrict__ wk,
                       const float* __restrict__ wv, const float* __restrict__ wp,
                       const float* __restrict__ f1, const float* __restrict__ f2){
    int total = 224*96 + 96*96 + 192*96 + 96*192;
    for (int idx=blockIdx.x*256+threadIdx.x; idx<total; idx+=gridDim.x*256){
        float v; int o=idx;
        if (o < 224*96){
            int n=o/96, k=o-n*96;
            v = (n<64)? wq[k*64+n] : (n<128)? wk[k*64+(n-64)] : wv[k*96+(n-128)];
        } else if ((o-=224*96) < 96*96){
            int n=o/96, k=o-n*96; v = wp[k*96+n];
        } else if ((o-=96*96) < 192*96){
            int n=o/96, k=o-n*96; v = f1[k*192+n];
        } else {
            o -= 192*96; int n=o/192, k=o-n*192; v = f2[k*96+n];
        }
        g_WT[idx] = tf32r(v);
    }
}

// K1: windowize + LN1
__global__ void k_win_ln(const float* __restrict__ x,
                         const float* __restrict__ w1, const float* __restrict__ b1){
    extern __shared__ float sm[];
    float* buf=sm; float* smean=sm+96*257; float* sinvv=smean+256;
    float* sw=sinvv+256; float* sb=sw+96;
    int w=blockIdx.x, b=w/NB, wd=w-b*NB;
    int top=wpos(wd/19), left=wpos(wd%19);
    int t=threadIdx.x;
    if (t<96){ sw[t]=w1[t]; sb[t]=b1[t]; }
    int py=top+(t>>4), px=left+(t&15);
    const float* xp = x + b*96*HW + py*256 + px;
    float s=0.f,s2=0.f;
    #pragma unroll 4
    for (int c=0;c<96;c++){ float v=xp[c*HW]; s+=v; s2+=v*v; buf[c*257+t]=v; }
    float mn=s*(1.f/96.f); float var=s2*(1.f/96.f)-mn*mn;
    smean[t]=mn; sinvv[t]=rsqrtf(var+1e-5f);
    __syncthreads();
    float* yo = g_Y + (size_t)w*256*96;
    for (int idx=t; idx<256*96; idx+=256){
        int tt=idx/96, cc=idx-tt*96;
        yo[idx]=(buf[cc*257+tt]-smean[tt])*sinvv[tt]*sw[cc]+sb[cc];
    }
}

// fills (KP = K+4 padded stride)
template<int K>
__device__ __forceinline__ void fillA(float* As, const float* src, int m0, int tid){
    for (int idx=tid; idx<128*K; idx+=256){
        int r=idx/K, k=idx-r*K;
        As[r*(K+4)+k] = tf32r(src[(size_t)(m0+r)*K + k]);
    }
}
template<int K,int N>
__device__ __forceinline__ void fillW(float* Ws, const float* WT, int tid){
    for (int idx=tid; idx<N*K; idx+=256){
        int n=idx/K, k=idx-n*K;
        Ws[n*(K+4)+k] = WT[idx];
    }
}
// mainloop: C[128 x NT*8] = A[128xK] * W^T, fragments per warp strip of 16 rows
template<int K,int NT>
__device__ __forceinline__ void lin_main(const float* As, const float* Ws,
                                         float (*acc)[4], int wid, int lane){
    const int KP=K+4;
    int g=lane>>2, t=lane&3;
    int r0=wid*16+g, r1=r0+8;
    #pragma unroll
    for (int k0=0;k0<K;k0+=8){
        unsigned a0=__float_as_uint(As[r0*KP + k0+t]);
        unsigned a1=__float_as_uint(As[r1*KP + k0+t]);
        unsigned a2=__float_as_uint(As[r0*KP + k0+t+4]);
        unsigned a3=__float_as_uint(As[r1*KP + k0+t+4]);
        #pragma unroll
        for (int nt=0;nt<NT;nt++){
            int n=nt*8+g;
            unsigned b0=__float_as_uint(Ws[n*KP + k0+t]);
            unsigned b1=__float_as_uint(Ws[n*KP + k0+t+4]);
            MMA_T(acc[nt],a0,a1,a2,a3,b0,b1);
        }
    }
}
// epilogue: fragments -> Cs[col*132 + row]
template<int NT>
__device__ __forceinline__ void epi(float* Cs, float (*acc)[4], int wid, int lane){
    int g=lane>>2, t=lane&3, lr=wid*16+g;
    #pragma unroll
    for (int nt=0;nt<NT;nt++){
        int c=nt*8+2*t;
        Cs[c*132+lr]=acc[nt][0];   Cs[(c+1)*132+lr]=acc[nt][1];
        Cs[c*132+lr+8]=acc[nt][2]; Cs[(c+1)*132+lr+8]=acc[nt][3];
    }
}

// K2: fused QKV (N=224)
__global__ __launch_bounds__(256) void k_qkv(){
    extern __shared__ float sm[];
    float* As=sm; float* Ws=sm+128*100; float* Cs=sm;
    int m0=blockIdx.x*128, tid=threadIdx.x, wid=tid>>5, lane=tid&31;
    fillA<96>(As, g_Y, m0, tid);
    fillW<96,224>(Ws, g_WT, tid);
    __syncthreads();
    float acc[28][4];
    #pragma unroll
    for (int i=0;i<28;i++){acc[i][0]=acc[i][1]=acc[i][2]=acc[i][3]=0.f;}
    lin_main<96,28>(As,Ws,acc,wid,lane);
    __syncthreads();
    epi<28>(Cs,acc,wid,lane);
    __syncthreads();
    for (int idx=tid; idx<128*224; idx+=256){
        int r=idx/224, c=idx-r*224;
        float v=Cs[c*132+r]; size_t row=m0+r;
        if (c<64) g_Q[row*64+c]=v;
        else if (c<128) g_K[row*64+c-64]=v;
        else g_V[row*96+c-128]=v;
    }
}

// K3: attention per (window, head)
__global__ __launch_bounds__(256) void k_attn(){
    extern __shared__ float sm[];
    float* qs=sm; float* kk=qs+5120; float* vv=kk+5120;
    float* Ss=vv+6144; float* och=Ss+128*260;
    int w=blockIdx.x, h=blockIdx.y, tid=threadIdx.x;
    int wid=tid>>5, lane=tid&31, g=lane>>2, t=lane&3;
    for (int idx=tid; idx<4096; idx+=256){
        int tok=idx>>4, d=idx&15;
        qs[tok*20+d]=tf32r(g_Q[(size_t)(w*256+tok)*64+h*16+d]*0.25f);
        kk[tok*20+d]=tf32r(g_K[(size_t)(w*256+tok)*64+h*16+d]);
    }
    for (int idx=tid; idx<6144; idx+=256){
        int tok=idx/24, d=idx-tok*24;
        vv[idx]=tf32r(g_V[(size_t)(w*256+tok)*96+h*24+d]);
    }
    __syncthreads();
    int lr=wid*16+g;
    for (int cb=0; cb<2; cb++){
        int qb=cb*128;
        float acc[32][4];
        #pragma unroll
        for (int nt=0;nt<32;nt++){acc[nt][0]=acc[nt][1]=acc[nt][2]=acc[nt][3]=0.f;}
        #pragma unroll
        for (int k0=0;k0<16;k0+=8){
            unsigned a0=__float_as_uint(qs[(qb+lr)*20+k0+t]);
            unsigned a1=__float_as_uint(qs[(qb+lr+8)*20+k0+t]);
            unsigned a2=__float_as_uint(qs[(qb+lr)*20+k0+t+4]);
            unsigned a3=__float_as_uint(qs[(qb+lr+8)*20+k0+t+4]);
            #pragma unroll
            for (int nt=0;nt<32;nt++){
                unsigned b0=__float_as_uint(kk[(nt*8+g)*20+k0+t]);
                unsigned b1=__float_as_uint(kk[(nt*8+g)*20+k0+t+4]);
                MMA_T(acc[nt],a0,a1,a2,a3,b0,b1);
            }
        }
        float mx0=-1e30f, mx1=-1e30f;
        #pragma unroll
        for (int nt=0;nt<32;nt++){
            mx0=fmaxf(mx0,fmaxf(acc[nt][0],acc[nt][1]));
            mx1=fmaxf(mx1,fmaxf(acc[nt][2],acc[nt][3]));
        }
        mx0=fmaxf(mx0,__shfl_xor_sync(~0u,mx0,1)); mx0=fmaxf(mx0,__shfl_xor_sync(~0u,mx0,2));
        mx1=fmaxf(mx1,__shfl_xor_sync(~0u,mx1,1)); mx1=fmaxf(mx1,__shfl_xor_sync(~0u,mx1,2));
        float s0=0.f,s1=0.f;
        #pragma unroll
        for (int nt=0;nt<32;nt++){
            acc[nt][0]=__expf(acc[nt][0]-mx0); acc[nt][1]=__expf(acc[nt][1]-mx0);
            acc[nt][2]=__expf(acc[nt][2]-mx1); acc[nt][3]=__expf(acc[nt][3]-mx1);
            s0+=acc[nt][0]+acc[nt][1]; s1+=acc[nt][2]+acc[nt][3];
        }
        s0+=__shfl_xor_sync(~0u,s0,1); s0+=__shfl_xor_sync(~0u,s0,2);
        s1+=__shfl_xor_sync(~0u,s1,1); s1+=__shfl_xor_sync(~0u,s1,2);
        float i0=1.f/s0, i1=1.f/s1;
        #pragma unroll
        for (int nt=0;nt<32;nt++){
            int c=nt*8+2*t;
            Ss[lr*260+c]  =tf32r(acc[nt][0]*i0); Ss[lr*260+c+1]  =tf32r(acc[nt][1]*i0);
            Ss[(lr+8)*260+c]=tf32r(acc[nt][2]*i1); Ss[(lr+8)*260+c+1]=tf32r(acc[nt][3]*i1);
        }
        __syncthreads();
        float o[3][4];
        #pragma unroll
        for (int nt=0;nt<3;nt++){o[nt][0]=o[nt][1]=o[nt][2]=o[nt][3]=0.f;}
        #pragma unroll 4
        for (int k0=0;k0<256;k0+=8){
            unsigned a0=__float_as_uint(Ss[lr*260+k0+t]);
            unsigned a1=__float_as_uint(Ss[(lr+8)*260+k0+t]);
            unsigned a2=__float_as_uint(Ss[lr*260+k0+t+4]);
            unsigned a3=__float_as_uint(Ss[(lr+8)*260+k0+t+4]);
            #pragma unroll
            for (int nt=0;nt<3;nt++){
                unsigned b0=__float_as_uint(vv[(k0+t)*24+nt*8+g]);
                unsigned b1=__float_as_uint(vv[(k0+t+4)*24+nt*8+g]);
                MMA_T(o[nt],a0,a1,a2,a3,b0,b1);
            }
        }
        #pragma unroll
        for (int nt=0;nt<3;nt++){
            int c=nt*8+2*t;
            och[lr*28+c]=o[nt][0];   och[lr*28+c+1]=o[nt][1];
            och[(lr+8)*28+c]=o[nt][2]; och[(lr+8)*28+c+1]=o[nt][3];
        }
        __syncthreads();
        for (int idx=tid; idx<128*24; idx+=256){
            int t2=idx/24, d2=idx-t2*24;
            g_AO[(size_t)(w*256+qb+t2)*96 + h*24 + d2] = och[t2*28+d2];
        }
        __syncthreads();
    }
}

// K4: proj GEMM
__global__ __launch_bounds__(256) void k_proj(){
    extern __shared__ float sm[];
    float* As=sm; float* Ws=sm+128*100; float* Cs=sm;
    int m0=blockIdx.x*128, tid=threadIdx.x, wid=tid>>5, lane=tid&31;
    fillA<96>(As, g_AO, m0, tid);
    fillW<96,96>(Ws, g_WT+224*96, tid);
    __syncthreads();
    float acc[12][4];
    #pragma unroll
    for (int i=0;i<12;i++){acc[i][0]=acc[i][1]=acc[i][2]=acc[i][3]=0.f;}
    lin_main<96,12>(As,Ws,acc,wid,lane);
    __syncthreads();
    epi<12>(Cs,acc,wid,lane);
    __syncthreads();
    for (int idx=tid; idx<128*96; idx+=256){
        int r=idx/96, c=idx-r*96;
        g_PO[(size_t)(m0+r)*96+c]=Cs[c*132+r];
    }
}

// K5: gather overlap-add -> ACC (token-major) and X2C (channel-major)
__global__ void k_gather(const float* __restrict__ x){
    int blk=blockIdx.x, b=blk>>8, y=blk&255, px=threadIdx.x;
    int tys[2], iys[2], nys=0, txs[2], ixs[2], nxs=0;
    int by=y/14, bx=px/14;
    #pragma unroll
    for (int d=-1; d<=1; d++){
        int i=by+d;
        if (i>=0 && i<=18){ int tp=wpos(i);
            if (tp<=y && y<tp+16){ if (!nys||tys[nys-1]!=tp){tys[nys]=tp; iys[nys]=i; nys++;} } }
    }
    #pragma unroll
    for (int d=-1; d<=1; d++){
        int i=bx+d;
        if (i>=0 && i<=18){ int tp=wpos(i);
            if (tp<=px && px<tp+16){ if (!nxs||txs[nxs-1]!=tp){txs[nxs]=tp; ixs[nxs]=i; nxs++;} } }
    }
    float f=1.0f/(float)(nys*nxs);
    size_t src[4]; int nsrc=0;
    for (int a=0;a<nys;a++)
        for (int c=0;c<nxs;c++){
            int wnd=b*NB+iys[a]*19+ixs[c];
            int tok=(y-tys[a])*16+(px-txs[c]);
            src[nsrc++]=((size_t)wnd*256+tok)*96;
        }
    size_t obase=(size_t)(b*HW+y*256+px)*96;
    size_t xbase=(size_t)b*96*HW + y*256 + px;
    for (int c=0;c<96;c+=4){
        float4 s=make_float4(0.f,0.f,0.f,0.f);
        for (int q=0;q<nsrc;q++){
            float4 v=*(const float4*)&g_PO[src[q]+c];
            s.x+=v.x; s.y+=v.y; s.z+=v.z; s.w+=v.w;
        }
        float4 o;
        o.x=s.x*f + x[xbase+(size_t)(c+0)*HW];
        o.y=s.y*f + x[xbase+(size_t)(c+1)*HW];
        o.z=s.z*f + x[xbase+(size_t)(c+2)*HW];
        o.w=s.w*f + x[xbase+(size_t)(c+3)*HW];
        *(float4*)&g_ACC[obase+c]=o;
        g_X2C[xbase+(size_t)(c+0)*HW]=o.x;
        g_X2C[xbase+(size_t)(c+1)*HW]=o.y;
        g_X2C[xbase+(size_t)(c+2)*HW]=o.z;
        g_X2C[xbase+(size_t)(c+3)*HW]=o.w;
    }
}

// K6: LN2
__global__ void k_ln2(const float* __restrict__ w2, const float* __restrict__ b2){
    int m=blockIdx.x*256+threadIdx.x;
    const float4* a4=(const float4*)(g_ACC+(size_t)m*96);
    float s=0.f,s2=0.f;
    #pragma unroll 4
    for (int q=0;q<24;q++){
        float4 v=a4[q];
        s+=v.x+v.y+v.z+v.w;
        s2+=v.x*v.x+v.y*v.y+v.z*v.z+v.w*v.w;
    }
    float mn=s*(1.f/96.f); float inv=rsqrtf(s2*(1.f/96.f)-mn*mn+1e-5f);
    float4* yo=(float4*)(g_YN+(size_t)m*96);
    const float4* w4=(const float4*)w2; const float4* bb4=(const float4*)b2;
    #pragma unroll 4
    for (int q=0;q<24;q++){
        float4 v=a4[q]; float4 wv=w4[q]; float4 bv=bb4[q];
        v.x=(v.x-mn)*inv*wv.x+bv.x; v.y=(v.y-mn)*inv*wv.y+bv.y;
        v.z=(v.z-mn)*inv*wv.z+bv.z; v.w=(v.w-mn)*inv*wv.w+bv.w;
        yo[q]=v;
    }
}

// K7: fc1 (N=192) + gelu, channel-major
__global__ __launch_bounds__(256) void k_fc1(const float* __restrict__ bias){
    extern __shared__ float sm[];
    float* As=sm; float* Ws=sm+128*100; float* Cs=sm;
    int m0=blockIdx.x*128, tid=threadIdx.x, wid=tid>>5, lane=tid&31;
    fillA<96>(As, g_YN, m0, tid);
    fillW<96,192>(Ws, g_WT+224*96+96*96, tid);
    __syncthreads();
    float acc[24][4];
    #pragma unroll
    for (int i=0;i<24;i++){acc[i][0]=acc[i][1]=acc[i][2]=acc[i][3]=0.f;}
    lin_main<96,24>(As,Ws,acc,wid,lane);
    __syncthreads();
    epi<24>(Cs,acc,wid,lane);
    __syncthreads();
    int b=m0>>16, p0=m0&65535;
    for (int idx=tid; idx<192*128; idx+=256){
        int c=idx>>7, r=idx&127;
        g_FC1[(size_t)(b*192+c)*HW+p0+r]=gelu_f(Cs[c*132+r]+bias[c]);
    }
}

// K8: depthwise 5x5 + gelu
__global__ void k_dw(const float* __restrict__ dwW, const float* __restrict__ dwB){
    __shared__ float swt[25];
    __shared__ float tile[12*260];
    int bc=blockIdx.x, ch=bc%192;
    int y0=blockIdx.y*8, t=threadIdx.x;
    if (t<25) swt[t]=dwW[ch*25+t];
    const float* src=g_FC1+(size_t)bc*HW;
    for (int idx=t; idx<3120; idx+=256){
        int rr=idx/260, cc=idx-rr*260;
        int gy=y0-2+rr, gx=cc-2;
        tile[idx]=(gy>=0 && gy<256 && (unsigned)gx<256u)?src[gy*256+gx]:0.f;
    }
    __syncthreads();
    float bias=dwB[ch];
    #pragma unroll
    for (int r=0;r<8;r++){
        float a=0.f;
        #pragma unroll
        for (int ky=0;ky<5;ky++)
            #pragma unroll
            for (int kx=0;kx<5;kx++)
                a+=tile[(r+ky)*260+t+kx]*swt[ky*5+kx];
        g_DW[(size_t)bc*HW+(y0+r)*256+t]=gelu_f(a+bias);
    }
}

// K9: fc2 (K=192) + bias + residual -> NCHW out
__global__ __launch_bounds__(256) void k_fc2(const float* __restrict__ bias,
                                             float* __restrict__ out){
    extern __shared__ float sm[];
    float* As=sm; float* Ws=sm+128*196; float* Cs=sm;
    int m0=blockIdx.x*128, tid=threadIdx.x, wid=tid>>5, lane=tid&31;
    int b=m0>>16, p0=m0&65535;
    for (int idx=tid; idx<128*192; idx+=256){
        int k=idx>>7, r=idx&127;
        size_t gi=(size_t)(b*192+k)*HW+p0+r;
        As[r*196+k]=tf32r(g_FC1[gi]+g_DW[gi]);
    }
    fillW<192,96>(Ws, g_WT+224*96+96*96+192*96, tid);
    __syncthreads();
    float acc[12][4];
    #pragma unroll
    for (int i=0;i<12;i++){acc[i][0]=acc[i][1]=acc[i][2]=acc[i][3]=0.f;}
    lin_main<192,12>(As,Ws,acc,wid,lane);
    __syncthreads();
    epi<12>(Cs,acc,wid,lane);
    __syncthreads();
    for (int idx=tid; idx<96*128; idx+=256){
        int c=idx>>7, r=idx&127;
        size_t gi=(size_t)(b*96+c)*HW+p0+r;
        out[gi]=Cs[c*132+r]+bias[c]+g_X2C[gi];
    }
}

static void setsm(const void* f, int bytes){
    cudaFuncSetAttribute(f, cudaFuncAttributeMaxDynamicSharedMemorySize, bytes);
}

extern "C" void kernel_launch(void* const* d_in, const int* in_sizes, int n_in,
                              void* d_out, int out_size){
    const float* x   =(const float*)d_in[0];
    const float* n1w =(const float*)d_in[1];
    const float* n1b =(const float*)d_in[2];
    const float* wq  =(const float*)d_in[3];
    const float* wk  =(const float*)d_in[4];
    const float* wv  =(const float*)d_in[5];
    const float* wpj =(const float*)d_in[6];
    const float* n2w =(const float*)d_in[7];
    const float* n2b =(const float*)d_in[8];
    const float* f1w =(const float*)d_in[9];
    const float* f1b =(const float*)d_in[10];
    const float* dww =(const float*)d_in[11];
    const float* dwb =(const float*)d_in[12];
    const float* f2w =(const float*)d_in[13];
    const float* f2b =(const float*)d_in[14];
    float* out=(float*)d_out;

    setsm((const void*)k_win_ln, 101504);
    setsm((const void*)k_qkv, 140800);
    setsm((const void*)k_attn, 212992);
    setsm((const void*)k_proj, 89600);
    setsm((const void*)k_fc1, 128000);
    setsm((const void*)k_fc2, 175616);

    k_prep<<<64,256>>>(wq,wk,wv,wpj,f1w,f2w);
    k_win_ln<<<BN,256,101504>>>(x,n1w,n1b);
    k_qkv<<<MTOK/128,256,140800>>>();
    k_attn<<<dim3(BN,4),256,212992>>>();
    k_proj<<<MTOK/128,256,89600>>>();
    k_gather<<<512,256>>>(x);
    k_ln2<<<512,256>>>(n2w,n2b);
    k_fc1<<<MTOK2/128,256,128000>>>(f1b);
    k_dw<<<dim3(384,32),256>>>(dww,dwb);
    k_fc2<<<MTOK2/128,256,175616>>>(f2b,out);
}